// round 7
// baseline (speedup 1.0000x reference)
#include <cuda_runtime.h>
#include <cuda_bf16.h>

// GuidedFilter (4,3,1024,1024) fp32, R=40, eps=1e-3.
// Warp-autonomous design: each warp owns 128 output cols but keeps vertical
// running sums over 256 extended cols (64-col halo each side), so the 81-wide
// horizontal window is fully warp-local: prefix scan + 2 shared loads per
// field per pixel, NO __syncthreads anywhere. 1-deep load pipeline per row.
// Slot map: prefix value for count k (1..256) lives at slot k + ((k-1)>>3)
// == 9*lane + j for k = 8*lane + j, matching the stride-9 scan stores.

#define HH   1024
#define WW   1024
#define NIMG 12
#define RAD  40
#define SEG  32
#define NTH  256
#define SIX(k) ((k) + (((k) - 1) >> 3))
#define EW   292            // > SIX(256) = 287

#define EPS 1e-3f

__device__ float g_a[(size_t)NIMG * HH * WW];
__device__ float g_b[(size_t)NIMG * HH * WW];

#define WSCAN(val)                                                    \
    {                                                                 \
        _Pragma("unroll")                                             \
        for (int o = 1; o < 32; o <<= 1) {                            \
            float _n = __shfl_up_sync(0xffffffffu, (val), o);         \
            if (lane >= o) (val) += _n;                               \
        }                                                             \
    }

// local prefix of 8 sums, warp scan, store slots 9*lane+1..+8 (stride-9, no conflicts)
#define SCAN_STORE(S, E)                                              \
    {                                                                 \
        float q0 = S[0];                                              \
        float q1 = q0 + S[1];                                         \
        float q2 = q1 + S[2];                                         \
        float q3 = q2 + S[3];                                         \
        float q4 = q3 + S[4];                                         \
        float q5 = q4 + S[5];                                         \
        float q6 = q5 + S[6];                                         \
        float q7 = q6 + S[7];                                         \
        float _t = q7, _inc = q7;                                     \
        WSCAN(_inc);                                                  \
        float _x = _inc - _t;                                         \
        float* _e = (E) + 9 * lane;                                   \
        _e[1] = _x + q0; _e[2] = _x + q1; _e[3] = _x + q2;            \
        _e[4] = _x + q3; _e[5] = _x + q4; _e[6] = _x + q5;            \
        _e[7] = _x + q6; _e[8] = _x + q7;                             \
    }

static __device__ __forceinline__ float4 zf4() { return make_float4(0.f, 0.f, 0.f, 0.f); }

// ---------------------------------------------------------------------------
// Stage 1: I,p -> box means of {I,p,Ip,II} -> a,b
// ---------------------------------------------------------------------------
__global__ __launch_bounds__(NTH, 3) void k_stage1(const float* __restrict__ I,
                                                   const float* __restrict__ P) {
    __shared__ float sE[4][8][EW];

    const int tid  = threadIdx.x;
    const int lane = tid & 31;
    const int w    = tid >> 5;
    const int img  = blockIdx.y;
    const int y0   = blockIdx.x * SEG;
    const size_t b4 = (size_t)img * HH * 256;

    const float4* __restrict__ I4 = (const float4*)I + b4;
    const float4* __restrict__ P4 = (const float4*)P + b4;
    float4* __restrict__ A4 = (float4*)g_a + b4;
    float4* __restrict__ B4 = (float4*)g_b + b4;

    // extended-column float4 indices (2 per lane); may be out of image -> zero
    const int e0 = 32 * w - 16 + 2 * lane;
    const bool v0 = (e0 >= 0) && (e0 < 256);
    const bool v1 = (e0 + 1 >= 0) && (e0 + 1 < 256);

    // gather indices for 4 owned cols
    int kloP[4], khiP[4];
    float cntx[4];
#pragma unroll
    for (int j = 0; j < 4; ++j) {
        int c  = 128 * w + 4 * lane + j;
        int lo = max(c - RAD, 0);
        int hi = min(c + RAD, WW - 1);
        int kl = lo - 128 * w + 64;       // >= 24
        int kh = hi - 128 * w + 64 + 1;   // <= 232
        kloP[j] = SIX(kl);
        khiP[j] = SIX(kh);
        cntx[j] = (float)(hi - lo + 1);
    }

    float sI[8], sP[8], sIp[8], sII[8];
#pragma unroll
    for (int j = 0; j < 8; ++j) { sI[j] = 0.f; sP[j] = 0.f; sIp[j] = 0.f; sII[j] = 0.f; }

    // preamble: rows [max(0,y0-40), min(H-1,y0+40)] inclusive -> sums = window(y0)
    const int ys = max(0, y0 - RAD);
    const int ye = min(HH - 1, y0 + RAD);
#pragma unroll 2
    for (int yy = ys; yy <= ye; ++yy) {
        const float4* rI = I4 + (size_t)yy * 256;
        const float4* rP = P4 + (size_t)yy * 256;
        float4 i0 = v0 ? rI[e0] : zf4();
        float4 i1 = v1 ? rI[e0 + 1] : zf4();
        float4 p0 = v0 ? rP[e0] : zf4();
        float4 p1 = v1 ? rP[e0 + 1] : zf4();
        const float* ia = &i0.x; const float* ib = &i1.x;
        const float* pa = &p0.x; const float* pb = &p1.x;
#pragma unroll
        for (int j = 0; j < 4; ++j) {
            sI[j] += ia[j];          sI[j + 4] += ib[j];
            sP[j] += pa[j];          sP[j + 4] += pb[j];
            sIp[j] += ia[j] * pa[j]; sIp[j + 4] += ib[j] * pb[j];
            sII[j] += ia[j] * ia[j]; sII[j + 4] += ib[j] * ib[j];
        }
    }

    float* __restrict__ E0 = sE[0][w];
    float* __restrict__ E1 = sE[1][w];
    float* __restrict__ E2 = sE[2][w];
    float* __restrict__ E3 = sE[3][w];

#pragma unroll 1
    for (int y = y0; y < y0 + SEG; ++y) {
        // issue next edge-row loads first (used only at loop bottom)
        const int yl = y + RAD + 1;           // leading row for window(y+1)
        const int yt = y - RAD;               // trailing row leaving window
        const bool okL = (yl < HH);
        const bool okT = (yt >= 0);
        const float4* rIL = I4 + (size_t)(okL ? yl : 0) * 256;
        const float4* rPL = P4 + (size_t)(okL ? yl : 0) * 256;
        const float4* rIT = I4 + (size_t)(okT ? yt : 0) * 256;
        const float4* rPT = P4 + (size_t)(okT ? yt : 0) * 256;
        float4 Li0 = (okL && v0) ? rIL[e0] : zf4();
        float4 Li1 = (okL && v1) ? rIL[e0 + 1] : zf4();
        float4 Lp0 = (okL && v0) ? rPL[e0] : zf4();
        float4 Lp1 = (okL && v1) ? rPL[e0 + 1] : zf4();
        float4 Ti0 = (okT && v0) ? rIT[e0] : zf4();
        float4 Ti1 = (okT && v1) ? rIT[e0 + 1] : zf4();
        float4 Tp0 = (okT && v0) ? rPT[e0] : zf4();
        float4 Tp1 = (okT && v1) ? rPT[e0 + 1] : zf4();

        // horizontal prefixes for window(y)
        SCAN_STORE(sI, E0);
        SCAN_STORE(sP, E1);
        SCAN_STORE(sIp, E2);
        SCAN_STORE(sII, E3);
        __syncwarp();

        const float cnty = (float)(min(y + RAD + 1, HH) - max(y - RAD, 0));
        float4 av, bv;
        float* ap = &av.x;
        float* bp = &bv.x;
#pragma unroll
        for (int j = 0; j < 4; ++j) {
            float u0 = E0[khiP[j]] - E0[kloP[j]];
            float u1 = E1[khiP[j]] - E1[kloP[j]];
            float u2 = E2[khiP[j]] - E2[kloP[j]];
            float u3 = E3[khiP[j]] - E3[kloP[j]];
            float inv = __fdividef(1.0f, cntx[j] * cnty);
            float mI  = u0 * inv;
            float mP  = u1 * inv;
            float mIp = u2 * inv;
            float mII = u3 * inv;
            float a = __fdividef(mIp - mI * mP, (mII - mI * mI) + EPS);
            ap[j] = a;
            bp[j] = mP - a * mI;
        }
        A4[(size_t)y * 256 + tid] = av;
        B4[(size_t)y * 256 + tid] = bv;
        __syncwarp();

        // advance sums -> window(y+1)
        const float* ia = &Li0.x; const float* ib = &Li1.x;
        const float* pa = &Lp0.x; const float* pb = &Lp1.x;
        const float* ta = &Ti0.x; const float* tb = &Ti1.x;
        const float* ua = &Tp0.x; const float* ub = &Tp1.x;
#pragma unroll
        for (int j = 0; j < 4; ++j) {
            sI[j]  += ia[j] - ta[j];
            sI[j + 4]  += ib[j] - tb[j];
            sP[j]  += pa[j] - ua[j];
            sP[j + 4]  += pb[j] - ub[j];
            sIp[j] += ia[j] * pa[j] - ta[j] * ua[j];
            sIp[j + 4] += ib[j] * pb[j] - tb[j] * ub[j];
            sII[j] += ia[j] * ia[j] - ta[j] * ta[j];
            sII[j + 4] += ib[j] * ib[j] - tb[j] * tb[j];
        }
    }
}

// ---------------------------------------------------------------------------
// Stage 2: a,b -> box means -> out = mean_a * I + mean_b
// ---------------------------------------------------------------------------
__global__ __launch_bounds__(NTH, 4) void k_stage2(const float* __restrict__ I,
                                                   float* __restrict__ out) {
    __shared__ float sE[2][8][EW];

    const int tid  = threadIdx.x;
    const int lane = tid & 31;
    const int w    = tid >> 5;
    const int img  = blockIdx.y;
    const int y0   = blockIdx.x * SEG;
    const size_t b4 = (size_t)img * HH * 256;

    const float4* __restrict__ A4 = (const float4*)g_a + b4;
    const float4* __restrict__ B4 = (const float4*)g_b + b4;
    const float4* __restrict__ I4 = (const float4*)I + b4;
    float4* __restrict__ O4 = (float4*)out + b4;

    const int e0 = 32 * w - 16 + 2 * lane;
    const bool v0 = (e0 >= 0) && (e0 < 256);
    const bool v1 = (e0 + 1 >= 0) && (e0 + 1 < 256);

    int kloP[4], khiP[4];
    float cntx[4];
#pragma unroll
    for (int j = 0; j < 4; ++j) {
        int c  = 128 * w + 4 * lane + j;
        int lo = max(c - RAD, 0);
        int hi = min(c + RAD, WW - 1);
        kloP[j] = SIX(lo - 128 * w + 64);
        khiP[j] = SIX(hi - 128 * w + 64 + 1);
        cntx[j] = (float)(hi - lo + 1);
    }

    float sA[8], sB[8];
#pragma unroll
    for (int j = 0; j < 8; ++j) { sA[j] = 0.f; sB[j] = 0.f; }

    const int ys = max(0, y0 - RAD);
    const int ye = min(HH - 1, y0 + RAD);
#pragma unroll 2
    for (int yy = ys; yy <= ye; ++yy) {
        const float4* rA = A4 + (size_t)yy * 256;
        const float4* rB = B4 + (size_t)yy * 256;
        float4 a0 = v0 ? rA[e0] : zf4();
        float4 a1 = v1 ? rA[e0 + 1] : zf4();
        float4 b0 = v0 ? rB[e0] : zf4();
        float4 b1 = v1 ? rB[e0 + 1] : zf4();
        const float* aa = &a0.x; const float* ab = &a1.x;
        const float* ba = &b0.x; const float* bb = &b1.x;
#pragma unroll
        for (int j = 0; j < 4; ++j) {
            sA[j] += aa[j]; sA[j + 4] += ab[j];
            sB[j] += ba[j]; sB[j + 4] += bb[j];
        }
    }

    float* __restrict__ E0 = sE[0][w];
    float* __restrict__ E1 = sE[1][w];

#pragma unroll 1
    for (int y = y0; y < y0 + SEG; ++y) {
        const int yl = y + RAD + 1;
        const int yt = y - RAD;
        const bool okL = (yl < HH);
        const bool okT = (yt >= 0);
        const float4* rAL = A4 + (size_t)(okL ? yl : 0) * 256;
        const float4* rBL = B4 + (size_t)(okL ? yl : 0) * 256;
        const float4* rAT = A4 + (size_t)(okT ? yt : 0) * 256;
        const float4* rBT = B4 + (size_t)(okT ? yt : 0) * 256;
        float4 La0 = (okL && v0) ? rAL[e0] : zf4();
        float4 La1 = (okL && v1) ? rAL[e0 + 1] : zf4();
        float4 Lb0 = (okL && v0) ? rBL[e0] : zf4();
        float4 Lb1 = (okL && v1) ? rBL[e0 + 1] : zf4();
        float4 Ta0 = (okT && v0) ? rAT[e0] : zf4();
        float4 Ta1 = (okT && v1) ? rAT[e0 + 1] : zf4();
        float4 Tb0 = (okT && v0) ? rBT[e0] : zf4();
        float4 Tb1 = (okT && v1) ? rBT[e0 + 1] : zf4();
        float4 i4 = I4[(size_t)y * 256 + tid];

        SCAN_STORE(sA, E0);
        SCAN_STORE(sB, E1);
        __syncwarp();

        const float cnty = (float)(min(y + RAD + 1, HH) - max(y - RAD, 0));
        const float* ip = &i4.x;
        float4 ov;
        float* op = &ov.x;
#pragma unroll
        for (int j = 0; j < 4; ++j) {
            float sa = E0[khiP[j]] - E0[kloP[j]];
            float sb = E1[khiP[j]] - E1[kloP[j]];
            float inv = __fdividef(1.0f, cntx[j] * cnty);
            op[j] = (sa * inv) * ip[j] + (sb * inv);
        }
        O4[(size_t)y * 256 + tid] = ov;
        __syncwarp();

        const float* aa = &La0.x; const float* ab = &La1.x;
        const float* ba = &Lb0.x; const float* bb = &Lb1.x;
        const float* ca = &Ta0.x; const float* cb = &Ta1.x;
        const float* da = &Tb0.x; const float* db = &Tb1.x;
#pragma unroll
        for (int j = 0; j < 4; ++j) {
            sA[j] += aa[j] - ca[j]; sA[j + 4] += ab[j] - cb[j];
            sB[j] += ba[j] - da[j]; sB[j + 4] += bb[j] - db[j];
        }
    }
}

extern "C" void kernel_launch(void* const* d_in, const int* in_sizes, int n_in,
                              void* d_out, int out_size) {
    const float* I = (const float*)d_in[0];
    const float* P = (const float*)d_in[1];
    float* out = (float*)d_out;

    dim3 g(HH / SEG, NIMG);
    k_stage1<<<g, NTH>>>(I, P);
    k_stage2<<<g, NTH>>>(I, out);
}

// round 8
// speedup vs baseline: 1.6947x; 1.6947x over previous
#include <cuda_runtime.h>
#include <cuda_fp16.h>
#include <cuda_bf16.h>

// GuidedFilter (4,3,1024,1024) fp32, R=40, eps=1e-3.
// R4 block design (8 warps x 128-col chunks, window<=2 chunks, 3 LDS/field/px,
// ONE barrier per row, double-buffered prefixes) with:
//   - SEG=16 (768 blocks -> ~5 resident blocks/SM, occ ~60%)
//   - a,b stored as interleaved half2 (one 4-byte word/pixel)

#define HH   1024
#define WW   1024
#define NIMG 12
#define RAD  40
#define SEG  16
#define NTH  256
#define CS   136               // padded chunk stride (PID(128)=132)
#define PID(k) ((k) + ((k) >> 5))
#define ESZ  (8 * CS)          // per field per buffer

#define EPS 1e-3f

struct __align__(16) H2x4 { __half2 v[4]; };

__device__ H2x4 g_ab[(size_t)NIMG * HH * 256];   // (a,b) per pixel, 4 px/entry

#define WSCAN(val)                                                    \
    {                                                                 \
        _Pragma("unroll")                                             \
        for (int o = 1; o < 32; o <<= 1) {                            \
            float _n = __shfl_up_sync(0xffffffffu, (val), o);         \
            if (lane >= o) (val) += _n;                               \
        }                                                             \
    }

// ---------------------------------------------------------------------------
// Stage 1: I,p -> box means of {I,p,Ip,II} -> a,b (half2)
// ---------------------------------------------------------------------------
__global__ __launch_bounds__(NTH) void k_stage1(const float* __restrict__ I,
                                                const float* __restrict__ P) {
    __shared__ float sE[2][4][ESZ];

    const int tid  = threadIdx.x;
    const int lane = tid & 31;
    const int w    = tid >> 5;
    const int img  = blockIdx.y;
    const int y0   = blockIdx.x * SEG;
    const size_t b4 = (size_t)img * HH * 256;

    const float4* __restrict__ I4 = (const float4*)I + b4;
    const float4* __restrict__ P4 = (const float4*)P + b4;
    H2x4* __restrict__ AB = g_ab + b4;

    const int c0 = tid * 4;

    int aLo[4], aHi[4], aT[4];
    float cntx[4];
#pragma unroll
    for (int j = 0; j < 4; ++j) {
        int c   = c0 + j;
        int lo  = max(c - RAD, 0);
        int hi1 = min(c + RAD, WW - 1);          // inclusive
        int ca  = lo >> 7;
        int cb  = hi1 >> 7;
        aLo[j]  = ca * CS + PID(lo & 127);
        aHi[j]  = cb * CS + PID((hi1 & 127) + 1);
        aT[j]   = ca * CS + ((cb > ca) ? PID(128) : 0);   // slot 0 of chunk == 0
        cntx[j] = (float)(hi1 + 1 - lo);
    }

    float4 rI = make_float4(0, 0, 0, 0);
    float4 rP = rI, rIp = rI, rII = rI;

    const int ys = max(0, y0 - RAD);
    const int ye = min(HH, y0 + RAD);            // exclusive
#pragma unroll 4
    for (int yy = ys; yy < ye; ++yy) {
        float4 i4 = I4[(size_t)yy * 256 + tid];
        float4 p4 = P4[(size_t)yy * 256 + tid];
        rI.x  += i4.x;        rI.y  += i4.y;        rI.z  += i4.z;        rI.w  += i4.w;
        rP.x  += p4.x;        rP.y  += p4.y;        rP.z  += p4.z;        rP.w  += p4.w;
        rIp.x += i4.x * p4.x; rIp.y += i4.y * p4.y; rIp.z += i4.z * p4.z; rIp.w += i4.w * p4.w;
        rII.x += i4.x * i4.x; rII.y += i4.y * i4.y; rII.z += i4.z * i4.z; rII.w += i4.w * i4.w;
    }

    const int eb = w * CS;
    const int k1 = lane * 4 + 1;
    const int sIdx0 = eb + PID(k1);
    const int sIdx1 = eb + PID(k1 + 1);
    const int sIdx2 = eb + PID(k1 + 2);
    const int sIdx3 = eb + PID(k1 + 3);

    for (int y = y0; y < y0 + SEG; ++y) {
        int ya = y + RAD;
        if (ya < HH) {
            float4 i4 = I4[(size_t)ya * 256 + tid];
            float4 p4 = P4[(size_t)ya * 256 + tid];
            rI.x  += i4.x;        rI.y  += i4.y;        rI.z  += i4.z;        rI.w  += i4.w;
            rP.x  += p4.x;        rP.y  += p4.y;        rP.z  += p4.z;        rP.w  += p4.w;
            rIp.x += i4.x * p4.x; rIp.y += i4.y * p4.y; rIp.z += i4.z * p4.z; rIp.w += i4.w * p4.w;
            rII.x += i4.x * i4.x; rII.y += i4.y * i4.y; rII.z += i4.z * i4.z; rII.w += i4.w * i4.w;
        }

        const int buf = y & 1;
        float* __restrict__ E0 = sE[buf][0];
        float* __restrict__ E1 = sE[buf][1];
        float* __restrict__ E2 = sE[buf][2];
        float* __restrict__ E3 = sE[buf][3];

        float4 pI, pP, pIp, pII;
        pI.x  = rI.x;  pI.y  = pI.x  + rI.y;  pI.z  = pI.y  + rI.z;  pI.w  = pI.z  + rI.w;
        pP.x  = rP.x;  pP.y  = pP.x  + rP.y;  pP.z  = pP.y  + rP.z;  pP.w  = pP.z  + rP.w;
        pIp.x = rIp.x; pIp.y = pIp.x + rIp.y; pIp.z = pIp.y + rIp.z; pIp.w = pIp.z + rIp.w;
        pII.x = rII.x; pII.y = pII.x + rII.y; pII.z = pII.y + rII.z; pII.w = pII.z + rII.w;

        float s0 = pI.w, s1 = pP.w, s2 = pIp.w, s3 = pII.w;
        float i0 = s0, i1 = s1, i2 = s2, i3 = s3;
        WSCAN(i0); WSCAN(i1); WSCAN(i2); WSCAN(i3);
        float x0 = i0 - s0, x1 = i1 - s1, x2 = i2 - s2, x3 = i3 - s3;

        if (lane == 0) { E0[eb] = 0.f; E1[eb] = 0.f; E2[eb] = 0.f; E3[eb] = 0.f; }
        E0[sIdx0] = x0 + pI.x;  E0[sIdx1] = x0 + pI.y;  E0[sIdx2] = x0 + pI.z;  E0[sIdx3] = x0 + pI.w;
        E1[sIdx0] = x1 + pP.x;  E1[sIdx1] = x1 + pP.y;  E1[sIdx2] = x1 + pP.z;  E1[sIdx3] = x1 + pP.w;
        E2[sIdx0] = x2 + pIp.x; E2[sIdx1] = x2 + pIp.y; E2[sIdx2] = x2 + pIp.z; E2[sIdx3] = x2 + pIp.w;
        E3[sIdx0] = x3 + pII.x; E3[sIdx1] = x3 + pII.y; E3[sIdx2] = x3 + pII.z; E3[sIdx3] = x3 + pII.w;

        __syncthreads();

        float cnty = (float)(min(y + RAD + 1, HH) - max(y - RAD, 0));
        H2x4 hv;
#pragma unroll
        for (int j = 0; j < 4; ++j) {
            float u0 = E0[aHi[j]] - E0[aLo[j]] + E0[aT[j]];
            float u1 = E1[aHi[j]] - E1[aLo[j]] + E1[aT[j]];
            float u2 = E2[aHi[j]] - E2[aLo[j]] + E2[aT[j]];
            float u3 = E3[aHi[j]] - E3[aLo[j]] + E3[aT[j]];
            float inv = __fdividef(1.0f, cntx[j] * cnty);
            float mI  = u0 * inv;
            float mP  = u1 * inv;
            float mIp = u2 * inv;
            float mII = u3 * inv;
            float a = __fdividef(mIp - mI * mP, (mII - mI * mI) + EPS);
            float b = mP - a * mI;
            hv.v[j] = __floats2half2_rn(a, b);
        }
        AB[(size_t)y * 256 + tid] = hv;

        int yr = y - RAD;
        if (yr >= 0) {
            float4 i4 = I4[(size_t)yr * 256 + tid];
            float4 p4 = P4[(size_t)yr * 256 + tid];
            rI.x  -= i4.x;        rI.y  -= i4.y;        rI.z  -= i4.z;        rI.w  -= i4.w;
            rP.x  -= p4.x;        rP.y  -= p4.y;        rP.z  -= p4.z;        rP.w  -= p4.w;
            rIp.x -= i4.x * p4.x; rIp.y -= i4.y * p4.y; rIp.z -= i4.z * p4.z; rIp.w -= i4.w * p4.w;
            rII.x -= i4.x * i4.x; rII.y -= i4.y * i4.y; rII.z -= i4.z * i4.z; rII.w -= i4.w * i4.w;
        }
    }
}

// ---------------------------------------------------------------------------
// Stage 2: a,b (half2) -> box means -> out = mean_a * I + mean_b
// ---------------------------------------------------------------------------
__global__ __launch_bounds__(NTH) void k_stage2(const float* __restrict__ I,
                                                float* __restrict__ out) {
    __shared__ float sE[2][2][ESZ];

    const int tid  = threadIdx.x;
    const int lane = tid & 31;
    const int w    = tid >> 5;
    const int img  = blockIdx.y;
    const int y0   = blockIdx.x * SEG;
    const size_t b4 = (size_t)img * HH * 256;

    const H2x4* __restrict__ AB = g_ab + b4;
    const float4* __restrict__ I4 = (const float4*)I + b4;
    float4* __restrict__ O4 = (float4*)out + b4;

    const int c0 = tid * 4;

    int aLo[4], aHi[4], aT[4];
    float cntx[4];
#pragma unroll
    for (int j = 0; j < 4; ++j) {
        int c   = c0 + j;
        int lo  = max(c - RAD, 0);
        int hi1 = min(c + RAD, WW - 1);
        int ca  = lo >> 7;
        int cb  = hi1 >> 7;
        aLo[j]  = ca * CS + PID(lo & 127);
        aHi[j]  = cb * CS + PID((hi1 & 127) + 1);
        aT[j]   = ca * CS + ((cb > ca) ? PID(128) : 0);
        cntx[j] = (float)(hi1 + 1 - lo);
    }

    float rA[4] = {0.f, 0.f, 0.f, 0.f};
    float rB[4] = {0.f, 0.f, 0.f, 0.f};

    const int ys = max(0, y0 - RAD);
    const int ye = min(HH, y0 + RAD);
#pragma unroll 4
    for (int yy = ys; yy < ye; ++yy) {
        H2x4 h = AB[(size_t)yy * 256 + tid];
#pragma unroll
        for (int j = 0; j < 4; ++j) {
            float2 f = __half22float2(h.v[j]);
            rA[j] += f.x;
            rB[j] += f.y;
        }
    }

    const int eb = w * CS;
    const int k1 = lane * 4 + 1;
    const int sIdx0 = eb + PID(k1);
    const int sIdx1 = eb + PID(k1 + 1);
    const int sIdx2 = eb + PID(k1 + 2);
    const int sIdx3 = eb + PID(k1 + 3);

    for (int y = y0; y < y0 + SEG; ++y) {
        int ya = y + RAD;
        if (ya < HH) {
            H2x4 h = AB[(size_t)ya * 256 + tid];
#pragma unroll
            for (int j = 0; j < 4; ++j) {
                float2 f = __half22float2(h.v[j]);
                rA[j] += f.x;
                rB[j] += f.y;
            }
        }

        const int buf = y & 1;
        float* __restrict__ E0 = sE[buf][0];
        float* __restrict__ E1 = sE[buf][1];

        float4 pA, pB;
        pA.x = rA[0]; pA.y = pA.x + rA[1]; pA.z = pA.y + rA[2]; pA.w = pA.z + rA[3];
        pB.x = rB[0]; pB.y = pB.x + rB[1]; pB.z = pB.y + rB[2]; pB.w = pB.z + rB[3];

        float s0 = pA.w, s1 = pB.w;
        float i0 = s0, i1 = s1;
        WSCAN(i0); WSCAN(i1);
        float x0 = i0 - s0, x1 = i1 - s1;

        if (lane == 0) { E0[eb] = 0.f; E1[eb] = 0.f; }
        E0[sIdx0] = x0 + pA.x; E0[sIdx1] = x0 + pA.y; E0[sIdx2] = x0 + pA.z; E0[sIdx3] = x0 + pA.w;
        E1[sIdx0] = x1 + pB.x; E1[sIdx1] = x1 + pB.y; E1[sIdx2] = x1 + pB.z; E1[sIdx3] = x1 + pB.w;

        __syncthreads();

        float cnty = (float)(min(y + RAD + 1, HH) - max(y - RAD, 0));
        float4 i4 = I4[(size_t)y * 256 + tid];
        const float* ip = &i4.x;
        float4 ov;
        float* op = &ov.x;
#pragma unroll
        for (int j = 0; j < 4; ++j) {
            float sa = E0[aHi[j]] - E0[aLo[j]] + E0[aT[j]];
            float sb = E1[aHi[j]] - E1[aLo[j]] + E1[aT[j]];
            float inv = __fdividef(1.0f, cntx[j] * cnty);
            op[j] = (sa * inv) * ip[j] + (sb * inv);
        }
        O4[(size_t)y * 256 + tid] = ov;

        int yr = y - RAD;
        if (yr >= 0) {
            H2x4 h = AB[(size_t)yr * 256 + tid];
#pragma unroll
            for (int j = 0; j < 4; ++j) {
                float2 f = __half22float2(h.v[j]);
                rA[j] -= f.x;
                rB[j] -= f.y;
            }
        }
    }
}

extern "C" void kernel_launch(void* const* d_in, const int* in_sizes, int n_in,
                              void* d_out, int out_size) {
    const float* I = (const float*)d_in[0];
    const float* P = (const float*)d_in[1];
    float* out = (float*)d_out;

    dim3 g(HH / SEG, NIMG);
    k_stage1<<<g, NTH>>>(I, P);
    k_stage2<<<g, NTH>>>(I, out);
}